// round 12
// baseline (speedup 1.0000x reference)
#include <cuda_runtime.h>
#include <cstdint>

#define NB 8
#define NC 512
#define NT 1024
#define NHEADS 8
#define NCH 64
#define NGROUPS 32
#define NGC 16

// ---------------- scratch (alloc-free: __device__ globals) ----------------
__device__ float g_xn[(size_t)NB * NC * NT];        // 16 MB, tf32 bits, natural [b][c][t]
__device__ float g_wq[(size_t)3 * NC * NC];         // 3 MB,  tf32 bits, A-frag-ready
__device__ float g_wp[(size_t)NC * NC];             // 1 MB,  tf32 bits, A-frag-ready
__device__ float g_qkv[(size_t)NB * 3 * NC * NT];   // 48 MB, tf32 bits, natural
__device__ float g_attn[(size_t)NB * NC * NT];      // 16 MB, tf32 bits, natural

// ---------------- helpers ----------------
__device__ __forceinline__ uint32_t f2tf32(float f) {
    uint32_t r;
    asm("cvt.rna.tf32.f32 %0, %1;" : "=r"(r) : "f"(f));
    return r;
}
__device__ __forceinline__ float tf32f(float f) { return __uint_as_float(f2tf32(f)); }
__device__ __forceinline__ float ex2f(float x) {
    float r;
    asm("ex2.approx.ftz.f32 %0, %1;" : "=f"(r) : "f"(x));
    return r;
}
__device__ __forceinline__ void mma_tf32(float* d, const uint32_t* a, const uint32_t* b) {
    asm volatile(
        "mma.sync.aligned.m16n8k8.row.col.f32.tf32.tf32.f32 "
        "{%0,%1,%2,%3}, {%4,%5,%6,%7}, {%8,%9}, {%0,%1,%2,%3};"
        : "+f"(d[0]), "+f"(d[1]), "+f"(d[2]), "+f"(d[3])
        : "r"(a[0]), "r"(a[1]), "r"(a[2]), "r"(a[3]), "r"(b[0]), "r"(b[1]));
}
__device__ __forceinline__ void cp16(uint32_t dst, const void* src) {
    asm volatile("cp.async.cg.shared.global [%0], [%1], 16;" :: "r"(dst), "l"(src));
}
__device__ __forceinline__ void cp_commit() {
    asm volatile("cp.async.commit_group;" ::: "memory");
}
template <int N>
__device__ __forceinline__ void cp_wait() {
    asm volatile("cp.async.wait_group %0;" :: "n"(N) : "memory");
}

// ---------------- weight permute (coalesced writes, L1-cached gathers) ----------------
__global__ __launch_bounds__(256) void wperm_kernel(const float* __restrict__ in,
                                                    float* __restrict__ out) {
    int tile = blockIdx.x;           // mt*16 + kt
    int mt = tile >> 4, kt = tile & 15;
    float* dst = out + ((size_t)tile << 12);
    #pragma unroll
    for (int r = 0; r < 4; r++) {
        int w = (threadIdx.x + (r << 8)) << 2;
        int ks = w >> 10, mb = (w >> 7) & 7, lane = (w >> 2) & 31;
        int qr = lane >> 2, qc = lane & 3;
        int m0 = mt * 128 + mb * 16 + qr;
        int k0 = kt * 32 + ks * 8 + qc;
        float4 o;
        o.x = tf32f(in[(size_t)m0 * NC + k0]);
        o.y = tf32f(in[(size_t)(m0 + 8) * NC + k0]);
        o.z = tf32f(in[(size_t)m0 * NC + k0 + 4]);
        o.w = tf32f(in[(size_t)(m0 + 8) * NC + k0 + 4]);
        *(float4*)(dst + w) = o;
    }
}

// ---------------- GroupNorm: stats + apply + tf32 convert ----------------
__global__ __launch_bounds__(256) void gn_kernel(const float* __restrict__ x,
                                                 const float* __restrict__ nw,
                                                 const float* __restrict__ nb) {
    int bg = blockIdx.x;
    int g = bg & (NGROUPS - 1);
    const float4* p4 = (const float4*)(x + (size_t)bg * NGC * NT);
    float4* o4 = (float4*)(g_xn + (size_t)bg * NGC * NT);
    float s = 0.f, ss = 0.f;
    for (int i = threadIdx.x; i < NGC * NT / 4; i += 256) {
        float4 v = p4[i];
        s  += v.x + v.y + v.z + v.w;
        ss += v.x * v.x + v.y * v.y + v.z * v.z + v.w * v.w;
    }
    __shared__ float sh[512];
    sh[threadIdx.x] = s;
    sh[256 + threadIdx.x] = ss;
    __syncthreads();
    for (int off = 128; off > 0; off >>= 1) {
        if (threadIdx.x < off) {
            sh[threadIdx.x]       += sh[threadIdx.x + off];
            sh[256 + threadIdx.x] += sh[256 + threadIdx.x + off];
        }
        __syncthreads();
    }
    float inv = 1.f / (float)(NGC * NT);
    float mu  = sh[0] * inv;
    float var = sh[256] * inv - mu * mu;
    float rs = rsqrtf(var + 1e-5f);
    for (int i = threadIdx.x; i < NGC * NT / 4; i += 256) {
        int c = g * NGC + (i >> 8);
        float sw = nw[c] * rs, sb = nb[c] - mu * sw;
        float4 v = p4[i];
        v.x = tf32f(v.x * sw + sb); v.y = tf32f(v.y * sw + sb);
        v.z = tf32f(v.z * sw + sb); v.w = tf32f(v.w * sw + sb);
        o4[i] = v;
    }
}

// ---------------- TF32 mma.sync GEMM, 3-stage cp.async (unchanged) ----------------
template <int MTOT, bool OUT_TF32, bool FUSE_RES>
__global__ __launch_bounds__(256, 2) void mma_gemm_kernel(
    const float* __restrict__ W, const float* __restrict__ Bsrc,
    const float* __restrict__ bias,
    const float* __restrict__ resid, float* __restrict__ Cout)
{
    extern __shared__ uint32_t smu[];
    const uint32_t sbase = (uint32_t)__cvta_generic_to_shared(smu);
    const int b = blockIdx.z, m0 = blockIdx.y << 7, n0 = blockIdx.x << 7;
    const float* Bb = Bsrc + (size_t)b * NC * NT;
    const float* Wt0 = W + ((size_t)(m0 >> 7) << 4 << 12);
    const int tid = threadIdx.x, lane = tid & 31, warp = tid >> 5;
    const int wm = warp >> 2, wn = warp & 3;
    const int qr = lane >> 2, qc = lane & 3;

    auto ISSUE = [&](int stage, int it) {
        uint32_t abase = sbase + (uint32_t)stage * 8448u * 4u;
        uint32_t bbase = abase + 4096u * 4u;
        const float* Wt = Wt0 + ((size_t)it << 12);
        const int k0 = it << 5;
        #pragma unroll
        for (int r = 0; r < 4; r++) {
            int idx = tid + (r << 8);
            cp16(abase + (uint32_t)idx * 16u, Wt + idx * 4);
            int k = idx >> 5, n4 = (idx & 31) << 2;
            cp16(bbase + ((uint32_t)k * 136u + n4) * 4u,
                 Bb + (size_t)(k0 + k) * NT + n0 + n4);
        }
    };

    float acc[4][4][4] = {};

    ISSUE(0, 0); cp_commit();
    ISSUE(1, 1); cp_commit();

    #pragma unroll 1
    for (int it = 0; it < 16; it++) {
        cp_wait<1>();
        __syncthreads();
        if (it + 2 < 16) ISSUE((it + 2) % 3, it + 2);
        cp_commit();

        const uint32_t* A  = smu + (it % 3) * 8448;
        const uint32_t* Bs = A + 4096;
        #pragma unroll
        for (int ks = 0; ks < 4; ks++) {
            uint4 af[4];
            uint32_t bf[4][2];
            #pragma unroll
            for (int mf = 0; mf < 4; mf++)
                af[mf] = *(const uint4*)&A[((ks * 8 + wm * 4 + mf) << 7) + (lane << 2)];
            #pragma unroll
            for (int nf = 0; nf < 4; nf++) {
                int n = wn * 32 + nf * 8 + qr, k = ks * 8 + qc;
                bf[nf][0] = Bs[k * 136 + n];
                bf[nf][1] = Bs[(k + 4) * 136 + n];
            }
            #pragma unroll
            for (int mf = 0; mf < 4; mf++)
                #pragma unroll
                for (int nf = 0; nf < 4; nf++)
                    mma_tf32(acc[mf][nf], (const uint32_t*)&af[mf], bf[nf]);
        }
    }

    #pragma unroll
    for (int mf = 0; mf < 4; mf++) {
        int m_r = m0 + wm * 64 + mf * 16 + qr;
        float bv0 = bias[m_r], bv1 = bias[m_r + 8];
        #pragma unroll
        for (int nf = 0; nf < 4; nf++) {
            int n = n0 + wn * 32 + nf * 8 + 2 * qc;
            float2 v0 = { acc[mf][nf][0] + bv0, acc[mf][nf][1] + bv0 };
            float2 v1 = { acc[mf][nf][2] + bv1, acc[mf][nf][3] + bv1 };
            if (FUSE_RES) {
                float2 r0 = *(const float2*)(resid + ((size_t)b * NC + m_r) * NT + n);
                float2 r1 = *(const float2*)(resid + ((size_t)b * NC + m_r + 8) * NT + n);
                v0.x += r0.x; v0.y += r0.y;
                v1.x += r1.x; v1.y += r1.y;
            }
            if (OUT_TF32) {
                v0.x = tf32f(v0.x); v0.y = tf32f(v0.y);
                v1.x = tf32f(v1.x); v1.y = tf32f(v1.y);
            }
            *(float2*)(Cout + ((size_t)b * MTOT + m_r) * NT + n) = v0;
            *(float2*)(Cout + ((size_t)b * MTOT + m_r + 8) * NT + n) = v1;
        }
    }
}

// ---------------- flash attention: cross-chunk S/PV software pipeline ----------------
// 128-q tile, 32 q/warp, 32-s chunks. Iteration j: S(j+1) + PV(j) in one block
// (independent -> scheduler interleaves; softmax latency hidden by PV mmas).
// P double-buffered. K ring mod 3, V ring mod 4 (prefetch j+3 must not hit V(j)).
// Deferred l: per-thread partials, quad-reduced once in epilogue.
// smem words: Pb 2x4608 [0,9216) (Q stage [64][132]=8448 overlaps at start),
//             K 3x2304 at 9216, V 4x2304 at 16128; total 25344.
__global__ __launch_bounds__(128, 2) void attn_kernel() {
    extern __shared__ uint32_t smw[];
    const uint32_t sbase = (uint32_t)__cvta_generic_to_shared(smw);
    uint32_t* const Pb[2] = { smw, smw + 4608 };
    uint32_t* const Ksl[3] = { smw + 9216, smw + 11520, smw + 13824 };
    uint32_t* const Vsl[4] = { smw + 16128, smw + 18432, smw + 20736, smw + 23040 };

    const int qt0 = blockIdx.x << 7;
    const int bh = blockIdx.y;
    const int b = bh >> 3, h = bh & 7;
    const float* qp = g_qkv + ((size_t)b * 3 * NC + (size_t)h * 3 * NCH) * NT;
    const float* kp = qp + (size_t)NCH * NT;
    const float* vp = kp + (size_t)NCH * NT;

    const int tid = threadIdx.x, lane = tid & 31, w = tid >> 5;
    const int qr = lane >> 2, qc = lane & 3;
    const int q0 = w << 5;

    auto ISSUE_KV = [&](int kslot, int vslot, int s0) {
        uint32_t kb = sbase + (9216u + (uint32_t)kslot * 2304u) * 4u;
        uint32_t vb = sbase + (16128u + (uint32_t)vslot * 2304u) * 4u;
        #pragma unroll
        for (int r = 0; r < 4; r++) {
            int idx = tid + (r << 7);
            int c = idx >> 3, s4 = (idx & 7) << 2;
            uint32_t off = ((uint32_t)c * 36u + s4) * 4u;
            cp16(kb + off, kp + (size_t)c * NT + s0 + s4);
            cp16(vb + off, vp + (size_t)c * NT + s0 + s4);
        }
    };

    // prologue: Q stage (group), chunk0 (group), chunk1 (group)
    #pragma unroll
    for (int r = 0; r < 16; r++) {
        int idx = tid + (r << 7);
        int c = idx >> 5, t4 = (idx & 31) << 2;
        cp16(sbase + ((uint32_t)c * 132u + t4) * 4u, qp + (size_t)c * NT + qt0 + t4);
    }
    cp_commit();
    ISSUE_KV(0, 0, 0);  cp_commit();
    ISSUE_KV(1, 1, 32); cp_commit();

    // hoist Q fragments, scaled by (1/8)*log2(e)
    const float SC = 0.18033688011f;
    cp_wait<2>();
    __syncthreads();
    uint32_t qf[2][8][4];
    #pragma unroll
    for (int ks = 0; ks < 8; ks++) {
        int c = ks * 8 + qc;
        #pragma unroll
        for (int mf = 0; mf < 2; mf++) {
            int qq = q0 + mf * 16 + qr;
            qf[mf][ks][0] = f2tf32(__uint_as_float(smw[c * 132 + qq]) * SC);
            qf[mf][ks][1] = f2tf32(__uint_as_float(smw[c * 132 + qq + 8]) * SC);
            qf[mf][ks][2] = f2tf32(__uint_as_float(smw[(c + 4) * 132 + qq]) * SC);
            qf[mf][ks][3] = f2tf32(__uint_as_float(smw[(c + 4) * 132 + qq + 8]) * SC);
        }
    }

    float m_i[2][2] = {{-1e30f, -1e30f}, {-1e30f, -1e30f}};
    float l_i[2][2] = {{0.f, 0.f}, {0.f, 0.f}};   // per-thread partials
    float o[2][8][4] = {};

    auto S_MMA = [&](const uint32_t* K, float (*sf)[4][4]) {
        #pragma unroll
        for (int ks = 0; ks < 8; ks++) {
            int c = ks * 8 + qc;
            #pragma unroll
            for (int nf = 0; nf < 4; nf++) {
                uint32_t bb[2];
                int s = nf * 8 + qr;
                bb[0] = K[c * 36 + s];
                bb[1] = K[(c + 4) * 36 + s];
                mma_tf32(sf[0][nf], qf[0][ks], bb);
                mma_tf32(sf[1][nf], qf[1][ks], bb);
            }
        }
    };
    auto PV_MMA = [&](const uint32_t* Pr, const uint32_t* V) {
        #pragma unroll
        for (int ks = 0; ks < 4; ks++) {
            int s = ks * 8 + qc;
            uint32_t a0[4], a1[4];
            int qq = q0 + qr;
            a0[0] = Pr[qq * 36 + s];      a0[1] = Pr[(qq + 8) * 36 + s];
            a0[2] = Pr[qq * 36 + s + 4];  a0[3] = Pr[(qq + 8) * 36 + s + 4];
            qq = q0 + 16 + qr;
            a1[0] = Pr[qq * 36 + s];      a1[1] = Pr[(qq + 8) * 36 + s];
            a1[2] = Pr[qq * 36 + s + 4];  a1[3] = Pr[(qq + 8) * 36 + s + 4];
            #pragma unroll
            for (int nf = 0; nf < 8; nf++) {
                uint32_t bb[2];
                int c = nf * 8 + qr;
                bb[0] = V[c * 36 + s];
                bb[1] = V[c * 36 + s + 4];
                mma_tf32(o[0][nf], a0, bb);
                mma_tf32(o[1][nf], a1, bb);
            }
        }
    };
    auto SOFTMAX_P = [&](float (*sf)[4][4], uint32_t* Pw) {
        #pragma unroll
        for (int mf = 0; mf < 2; mf++) {
            float mx0 = -1e30f, mx1 = -1e30f;
            #pragma unroll
            for (int nf = 0; nf < 4; nf++) {
                mx0 = fmaxf(mx0, fmaxf(sf[mf][nf][0], sf[mf][nf][1]));
                mx1 = fmaxf(mx1, fmaxf(sf[mf][nf][2], sf[mf][nf][3]));
            }
            #pragma unroll
            for (int off = 1; off <= 2; off <<= 1) {
                mx0 = fmaxf(mx0, __shfl_xor_sync(0xffffffffu, mx0, off));
                mx1 = fmaxf(mx1, __shfl_xor_sync(0xffffffffu, mx1, off));
            }
            float nm0 = fmaxf(m_i[mf][0], mx0), nm1 = fmaxf(m_i[mf][1], mx1);
            float corr0 = ex2f(m_i[mf][0] - nm0), corr1 = ex2f(m_i[mf][1] - nm1);
            m_i[mf][0] = nm0; m_i[mf][1] = nm1;
            float lp0 = 0.f, lp1 = 0.f;
            #pragma unroll
            for (int nf = 0; nf < 4; nf++) {
                sf[mf][nf][0] = ex2f(sf[mf][nf][0] - nm0);
                sf[mf][nf][1] = ex2f(sf[mf][nf][1] - nm0);
                sf[mf][nf][2] = ex2f(sf[mf][nf][2] - nm1);
                sf[mf][nf][3] = ex2f(sf[mf][nf][3] - nm1);
                lp0 += sf[mf][nf][0] + sf[mf][nf][1];
                lp1 += sf[mf][nf][2] + sf[mf][nf][3];
            }
            l_i[mf][0] = l_i[mf][0] * corr0 + lp0;   // per-thread partial; quad-reduce deferred
            l_i[mf][1] = l_i[mf][1] * corr1 + lp1;
            #pragma unroll
            for (int nf = 0; nf < 8; nf++) {
                o[mf][nf][0] *= corr0; o[mf][nf][1] *= corr0;
                o[mf][nf][2] *= corr1; o[mf][nf][3] *= corr1;
            }
            int qq = q0 + mf * 16 + qr;
            #pragma unroll
            for (int nf = 0; nf < 4; nf++) {
                int sc = nf * 8 + 2 * qc;
                *(uint2*)&Pw[qq * 36 + sc] =
                    make_uint2(f2tf32(sf[mf][nf][0]), f2tf32(sf[mf][nf][1]));
                *(uint2*)&Pw[(qq + 8) * 36 + sc] =
                    make_uint2(f2tf32(sf[mf][nf][2]), f2tf32(sf[mf][nf][3]));
            }
        }
        __syncwarp();
    };

    // chunk 0: S + softmax only (pipeline fill)
    cp_wait<1>();
    __syncthreads();   // chunk0 KV ready; also fences Q-hoist reads before Pb[0] writes
    {
        float sf[2][4][4] = {};
        S_MMA(Ksl[0], sf);
        SOFTMAX_P(sf, Pb[0]);
    }
    ISSUE_KV(2, 2, 64);
    cp_commit();

    // steady state: iteration j does S(j+1) + PV(j)
    #pragma unroll 1
    for (int j = 0; j < 31; j++) {
        if (j < 30) { cp_wait<1>(); } else { cp_wait<0>(); }
        __syncthreads();   // K(j+1)/V ready; fences readers of reused ring slots

        float sf[2][4][4] = {};
        S_MMA(Ksl[(j + 1) % 3], sf);
        PV_MMA(Pb[j & 1], Vsl[j & 3]);
        SOFTMAX_P(sf, Pb[(j + 1) & 1]);

        if (j + 3 < 32) ISSUE_KV((j + 3) % 3, (j + 3) & 3, (j + 3) << 5);
        cp_commit();
    }
    // drain: PV for chunk 31
    PV_MMA(Pb[1], Vsl[3]);

    // ---- epilogue: quad-reduce l, normalize, stage [c][t] stride 132, store ----
    float inv[2][2];
    #pragma unroll
    for (int mf = 0; mf < 2; mf++)
        #pragma unroll
        for (int r2 = 0; r2 < 2; r2++) {
            float l = l_i[mf][r2];
            l += __shfl_xor_sync(0xffffffffu, l, 1);
            l += __shfl_xor_sync(0xffffffffu, l, 2);
            inv[mf][r2] = 1.f / l;
        }
    __syncthreads();   // all warps done with P buffers before O staging reuse
    float* Os = (float*)smw;
    #pragma unroll
    for (int mf = 0; mf < 2; mf++) {
        float i0 = inv[mf][0], i1 = inv[mf][1];
        int qq = q0 + mf * 16 + qr;
        #pragma unroll
        for (int nf = 0; nf < 8; nf++) {
            int c = nf * 8 + 2 * qc;
            Os[c * 132 + qq]           = tf32f(o[mf][nf][0] * i0);
            Os[(c + 1) * 132 + qq]     = tf32f(o[mf][nf][1] * i0);
            Os[c * 132 + qq + 8]       = tf32f(o[mf][nf][2] * i1);
            Os[(c + 1) * 132 + qq + 8] = tf32f(o[mf][nf][3] * i1);
        }
    }
    __syncthreads();
    float* outp = g_attn + ((size_t)b * NC + (size_t)h * NCH) * NT;
    #pragma unroll
    for (int r = 0; r < 16; r++) {
        int idx = tid + (r << 7);
        int c = idx >> 5, t4 = (idx & 31) << 2;
        *(float4*)(outp + (size_t)c * NT + qt0 + t4) = *(const float4*)&Os[c * 132 + t4];
    }
}

// ---------------- launch ----------------
extern "C" void kernel_launch(void* const* d_in, const int* in_sizes, int n_in,
                              void* d_out, int out_size) {
    const float* x      = (const float*)d_in[0];
    const float* norm_w = (const float*)d_in[1];
    const float* norm_b = (const float*)d_in[2];
    const float* qkv_w  = (const float*)d_in[3];
    const float* qkv_b  = (const float*)d_in[4];
    const float* proj_w = (const float*)d_in[5];
    const float* proj_b = (const float*)d_in[6];
    float* out = (float*)d_out;

    float *xn_p, *wq_p, *wp_p, *qkv_p, *attn_p;
    cudaGetSymbolAddress((void**)&xn_p, g_xn);
    cudaGetSymbolAddress((void**)&wq_p, g_wq);
    cudaGetSymbolAddress((void**)&wp_p, g_wp);
    cudaGetSymbolAddress((void**)&qkv_p, g_qkv);
    cudaGetSymbolAddress((void**)&attn_p, g_attn);

    const int gemm_smem = 3 * 8448 * 4;   // 101376
    cudaFuncSetAttribute(mma_gemm_kernel<3 * NC, true, false>,
                         cudaFuncAttributeMaxDynamicSharedMemorySize, gemm_smem);
    cudaFuncSetAttribute(mma_gemm_kernel<NC, false, true>,
                         cudaFuncAttributeMaxDynamicSharedMemorySize, gemm_smem);
    const int attn_smem = 25344 * 4;      // 101376
    cudaFuncSetAttribute(attn_kernel, cudaFuncAttributeMaxDynamicSharedMemorySize, attn_smem);

    wperm_kernel<<<(3 * NC / 128) * 16, 256>>>(qkv_w, wq_p);
    wperm_kernel<<<(NC / 128) * 16, 256>>>(proj_w, wp_p);
    gn_kernel<<<NB * NGROUPS, 256>>>(x, norm_w, norm_b);

    dim3 gq(NT / 128, (3 * NC) / 128, NB);
    mma_gemm_kernel<3 * NC, true, false><<<gq, 256, gemm_smem>>>(
        wq_p, xn_p, qkv_b, nullptr, qkv_p);

    dim3 ga(NT / 128, NB * NHEADS);
    attn_kernel<<<ga, 128, attn_smem>>>();

    dim3 gp(NT / 128, NC / 128, NB);
    mma_gemm_kernel<NC, false, true><<<gp, 256, gemm_smem>>>(
        wp_p, attn_p, proj_b, x, out);
}

// round 13
// speedup vs baseline: 1.0001x; 1.0001x over previous
#include <cuda_runtime.h>
#include <cstdint>

#define NB 8
#define NC 512
#define NT 1024
#define NHEADS 8
#define NCH 64
#define NGROUPS 32
#define NGC 16

// ---------------- scratch (alloc-free: __device__ globals) ----------------
__device__ float g_xn[(size_t)NB * NC * NT];        // 16 MB, tf32 bits, natural [b][c][t]
__device__ float g_wq[(size_t)3 * NC * NC];         // 3 MB,  tf32 bits, A-frag-ready
__device__ float g_wp[(size_t)NC * NC];             // 1 MB,  tf32 bits, A-frag-ready
__device__ float g_qkv[(size_t)NB * 3 * NC * NT];   // 48 MB, tf32 bits, natural
__device__ float g_attn[(size_t)NB * NC * NT];      // 16 MB, tf32 bits, natural

// ---------------- helpers ----------------
__device__ __forceinline__ uint32_t f2tf32(float f) {
    uint32_t r;
    asm("cvt.rna.tf32.f32 %0, %1;" : "=r"(r) : "f"(f));
    return r;
}
__device__ __forceinline__ float tf32f(float f) { return __uint_as_float(f2tf32(f)); }
__device__ __forceinline__ float ex2f(float x) {
    float r;
    asm("ex2.approx.ftz.f32 %0, %1;" : "=f"(r) : "f"(x));
    return r;
}
__device__ __forceinline__ void mma_tf32(float* d, const uint32_t* a, const uint32_t* b) {
    asm volatile(
        "mma.sync.aligned.m16n8k8.row.col.f32.tf32.tf32.f32 "
        "{%0,%1,%2,%3}, {%4,%5,%6,%7}, {%8,%9}, {%0,%1,%2,%3};"
        : "+f"(d[0]), "+f"(d[1]), "+f"(d[2]), "+f"(d[3])
        : "r"(a[0]), "r"(a[1]), "r"(a[2]), "r"(a[3]), "r"(b[0]), "r"(b[1]));
}
__device__ __forceinline__ void cp16(uint32_t dst, const void* src) {
    asm volatile("cp.async.cg.shared.global [%0], [%1], 16;" :: "r"(dst), "l"(src));
}
__device__ __forceinline__ void cp_commit() {
    asm volatile("cp.async.commit_group;" ::: "memory");
}
template <int N>
__device__ __forceinline__ void cp_wait() {
    asm volatile("cp.async.wait_group %0;" :: "n"(N) : "memory");
}

// ---------------- weight permute (coalesced writes, L1-cached gathers) ----------------
__global__ __launch_bounds__(256) void wperm_kernel(const float* __restrict__ in,
                                                    float* __restrict__ out) {
    int tile = blockIdx.x;           // mt*16 + kt
    int mt = tile >> 4, kt = tile & 15;
    float* dst = out + ((size_t)tile << 12);
    #pragma unroll
    for (int r = 0; r < 4; r++) {
        int w = (threadIdx.x + (r << 8)) << 2;
        int ks = w >> 10, mb = (w >> 7) & 7, lane = (w >> 2) & 31;
        int qr = lane >> 2, qc = lane & 3;
        int m0 = mt * 128 + mb * 16 + qr;
        int k0 = kt * 32 + ks * 8 + qc;
        float4 o;
        o.x = tf32f(in[(size_t)m0 * NC + k0]);
        o.y = tf32f(in[(size_t)(m0 + 8) * NC + k0]);
        o.z = tf32f(in[(size_t)m0 * NC + k0 + 4]);
        o.w = tf32f(in[(size_t)(m0 + 8) * NC + k0 + 4]);
        *(float4*)(dst + w) = o;
    }
}

// ---------------- GroupNorm: stats + apply + tf32 convert ----------------
__global__ __launch_bounds__(256) void gn_kernel(const float* __restrict__ x,
                                                 const float* __restrict__ nw,
                                                 const float* __restrict__ nb) {
    int bg = blockIdx.x;
    int g = bg & (NGROUPS - 1);
    const float4* p4 = (const float4*)(x + (size_t)bg * NGC * NT);
    float4* o4 = (float4*)(g_xn + (size_t)bg * NGC * NT);
    float s = 0.f, ss = 0.f;
    for (int i = threadIdx.x; i < NGC * NT / 4; i += 256) {
        float4 v = p4[i];
        s  += v.x + v.y + v.z + v.w;
        ss += v.x * v.x + v.y * v.y + v.z * v.z + v.w * v.w;
    }
    __shared__ float sh[512];
    sh[threadIdx.x] = s;
    sh[256 + threadIdx.x] = ss;
    __syncthreads();
    for (int off = 128; off > 0; off >>= 1) {
        if (threadIdx.x < off) {
            sh[threadIdx.x]       += sh[threadIdx.x + off];
            sh[256 + threadIdx.x] += sh[256 + threadIdx.x + off];
        }
        __syncthreads();
    }
    float inv = 1.f / (float)(NGC * NT);
    float mu  = sh[0] * inv;
    float var = sh[256] * inv - mu * mu;
    float rs = rsqrtf(var + 1e-5f);
    for (int i = threadIdx.x; i < NGC * NT / 4; i += 256) {
        int c = g * NGC + (i >> 8);
        float sw = nw[c] * rs, sb = nb[c] - mu * sw;
        float4 v = p4[i];
        v.x = tf32f(v.x * sw + sb); v.y = tf32f(v.y * sw + sb);
        v.z = tf32f(v.z * sw + sb); v.w = tf32f(v.w * sw + sb);
        o4[i] = v;
    }
}

// ---------------- TF32 mma.sync GEMM, 3-stage cp.async (unchanged) ----------------
template <int MTOT, bool OUT_TF32, bool FUSE_RES>
__global__ __launch_bounds__(256, 2) void mma_gemm_kernel(
    const float* __restrict__ W, const float* __restrict__ Bsrc,
    const float* __restrict__ bias,
    const float* __restrict__ resid, float* __restrict__ Cout)
{
    extern __shared__ uint32_t smu[];
    const uint32_t sbase = (uint32_t)__cvta_generic_to_shared(smu);
    const int b = blockIdx.z, m0 = blockIdx.y << 7, n0 = blockIdx.x << 7;
    const float* Bb = Bsrc + (size_t)b * NC * NT;
    const float* Wt0 = W + ((size_t)(m0 >> 7) << 4 << 12);
    const int tid = threadIdx.x, lane = tid & 31, warp = tid >> 5;
    const int wm = warp >> 2, wn = warp & 3;
    const int qr = lane >> 2, qc = lane & 3;

    auto ISSUE = [&](int stage, int it) {
        uint32_t abase = sbase + (uint32_t)stage * 8448u * 4u;
        uint32_t bbase = abase + 4096u * 4u;
        const float* Wt = Wt0 + ((size_t)it << 12);
        const int k0 = it << 5;
        #pragma unroll
        for (int r = 0; r < 4; r++) {
            int idx = tid + (r << 8);
            cp16(abase + (uint32_t)idx * 16u, Wt + idx * 4);
            int k = idx >> 5, n4 = (idx & 31) << 2;
            cp16(bbase + ((uint32_t)k * 136u + n4) * 4u,
                 Bb + (size_t)(k0 + k) * NT + n0 + n4);
        }
    };

    float acc[4][4][4] = {};

    ISSUE(0, 0); cp_commit();
    ISSUE(1, 1); cp_commit();

    #pragma unroll 1
    for (int it = 0; it < 16; it++) {
        cp_wait<1>();
        __syncthreads();
        if (it + 2 < 16) ISSUE((it + 2) % 3, it + 2);
        cp_commit();

        const uint32_t* A  = smu + (it % 3) * 8448;
        const uint32_t* Bs = A + 4096;
        #pragma unroll
        for (int ks = 0; ks < 4; ks++) {
            uint4 af[4];
            uint32_t bf[4][2];
            #pragma unroll
            for (int mf = 0; mf < 4; mf++)
                af[mf] = *(const uint4*)&A[((ks * 8 + wm * 4 + mf) << 7) + (lane << 2)];
            #pragma unroll
            for (int nf = 0; nf < 4; nf++) {
                int n = wn * 32 + nf * 8 + qr, k = ks * 8 + qc;
                bf[nf][0] = Bs[k * 136 + n];
                bf[nf][1] = Bs[(k + 4) * 136 + n];
            }
            #pragma unroll
            for (int mf = 0; mf < 4; mf++)
                #pragma unroll
                for (int nf = 0; nf < 4; nf++)
                    mma_tf32(acc[mf][nf], (const uint32_t*)&af[mf], bf[nf]);
        }
    }

    #pragma unroll
    for (int mf = 0; mf < 4; mf++) {
        int m_r = m0 + wm * 64 + mf * 16 + qr;
        float bv0 = bias[m_r], bv1 = bias[m_r + 8];
        #pragma unroll
        for (int nf = 0; nf < 4; nf++) {
            int n = n0 + wn * 32 + nf * 8 + 2 * qc;
            float2 v0 = { acc[mf][nf][0] + bv0, acc[mf][nf][1] + bv0 };
            float2 v1 = { acc[mf][nf][2] + bv1, acc[mf][nf][3] + bv1 };
            if (FUSE_RES) {
                float2 r0 = *(const float2*)(resid + ((size_t)b * NC + m_r) * NT + n);
                float2 r1 = *(const float2*)(resid + ((size_t)b * NC + m_r + 8) * NT + n);
                v0.x += r0.x; v0.y += r0.y;
                v1.x += r1.x; v1.y += r1.y;
            }
            if (OUT_TF32) {
                v0.x = tf32f(v0.x); v0.y = tf32f(v0.y);
                v1.x = tf32f(v1.x); v1.y = tf32f(v1.y);
            }
            *(float2*)(Cout + ((size_t)b * MTOT + m_r) * NT + n) = v0;
            *(float2*)(Cout + ((size_t)b * MTOT + m_r + 8) * NT + n) = v1;
        }
    }
}

// ---------------- flash attention: cross-chunk S/PV software pipeline ----------------
// 128-q tile, 32 q/warp, 32-s chunks. Iteration j: S(j+1) + PV(j) in one block
// (independent -> scheduler interleaves; softmax latency hidden by PV mmas).
// P double-buffered. K ring mod 3, V ring mod 4 (prefetch j+3 must not hit V(j)).
// Deferred l: per-thread partials, quad-reduced once in epilogue.
// smem words: Pb 2x4608 [0,9216) (Q stage [64][132]=8448 overlaps at start),
//             K 3x2304 at 9216, V 4x2304 at 16128; total 25344.
__global__ __launch_bounds__(128, 2) void attn_kernel() {
    extern __shared__ uint32_t smw[];
    const uint32_t sbase = (uint32_t)__cvta_generic_to_shared(smw);
    uint32_t* const Pb[2] = { smw, smw + 4608 };
    uint32_t* const Ksl[3] = { smw + 9216, smw + 11520, smw + 13824 };
    uint32_t* const Vsl[4] = { smw + 16128, smw + 18432, smw + 20736, smw + 23040 };

    const int qt0 = blockIdx.x << 7;
    const int bh = blockIdx.y;
    const int b = bh >> 3, h = bh & 7;
    const float* qp = g_qkv + ((size_t)b * 3 * NC + (size_t)h * 3 * NCH) * NT;
    const float* kp = qp + (size_t)NCH * NT;
    const float* vp = kp + (size_t)NCH * NT;

    const int tid = threadIdx.x, lane = tid & 31, w = tid >> 5;
    const int qr = lane >> 2, qc = lane & 3;
    const int q0 = w << 5;

    auto ISSUE_KV = [&](int kslot, int vslot, int s0) {
        uint32_t kb = sbase + (9216u + (uint32_t)kslot * 2304u) * 4u;
        uint32_t vb = sbase + (16128u + (uint32_t)vslot * 2304u) * 4u;
        #pragma unroll
        for (int r = 0; r < 4; r++) {
            int idx = tid + (r << 7);
            int c = idx >> 3, s4 = (idx & 7) << 2;
            uint32_t off = ((uint32_t)c * 36u + s4) * 4u;
            cp16(kb + off, kp + (size_t)c * NT + s0 + s4);
            cp16(vb + off, vp + (size_t)c * NT + s0 + s4);
        }
    };

    // prologue: Q stage (group), chunk0 (group), chunk1 (group)
    #pragma unroll
    for (int r = 0; r < 16; r++) {
        int idx = tid + (r << 7);
        int c = idx >> 5, t4 = (idx & 31) << 2;
        cp16(sbase + ((uint32_t)c * 132u + t4) * 4u, qp + (size_t)c * NT + qt0 + t4);
    }
    cp_commit();
    ISSUE_KV(0, 0, 0);  cp_commit();
    ISSUE_KV(1, 1, 32); cp_commit();

    // hoist Q fragments, scaled by (1/8)*log2(e)
    const float SC = 0.18033688011f;
    cp_wait<2>();
    __syncthreads();
    uint32_t qf[2][8][4];
    #pragma unroll
    for (int ks = 0; ks < 8; ks++) {
        int c = ks * 8 + qc;
        #pragma unroll
        for (int mf = 0; mf < 2; mf++) {
            int qq = q0 + mf * 16 + qr;
            qf[mf][ks][0] = f2tf32(__uint_as_float(smw[c * 132 + qq]) * SC);
            qf[mf][ks][1] = f2tf32(__uint_as_float(smw[c * 132 + qq + 8]) * SC);
            qf[mf][ks][2] = f2tf32(__uint_as_float(smw[(c + 4) * 132 + qq]) * SC);
            qf[mf][ks][3] = f2tf32(__uint_as_float(smw[(c + 4) * 132 + qq + 8]) * SC);
        }
    }

    float m_i[2][2] = {{-1e30f, -1e30f}, {-1e30f, -1e30f}};
    float l_i[2][2] = {{0.f, 0.f}, {0.f, 0.f}};   // per-thread partials
    float o[2][8][4] = {};

    auto S_MMA = [&](const uint32_t* K, float (*sf)[4][4]) {
        #pragma unroll
        for (int ks = 0; ks < 8; ks++) {
            int c = ks * 8 + qc;
            #pragma unroll
            for (int nf = 0; nf < 4; nf++) {
                uint32_t bb[2];
                int s = nf * 8 + qr;
                bb[0] = K[c * 36 + s];
                bb[1] = K[(c + 4) * 36 + s];
                mma_tf32(sf[0][nf], qf[0][ks], bb);
                mma_tf32(sf[1][nf], qf[1][ks], bb);
            }
        }
    };
    auto PV_MMA = [&](const uint32_t* Pr, const uint32_t* V) {
        #pragma unroll
        for (int ks = 0; ks < 4; ks++) {
            int s = ks * 8 + qc;
            uint32_t a0[4], a1[4];
            int qq = q0 + qr;
            a0[0] = Pr[qq * 36 + s];      a0[1] = Pr[(qq + 8) * 36 + s];
            a0[2] = Pr[qq * 36 + s + 4];  a0[3] = Pr[(qq + 8) * 36 + s + 4];
            qq = q0 + 16 + qr;
            a1[0] = Pr[qq * 36 + s];      a1[1] = Pr[(qq + 8) * 36 + s];
            a1[2] = Pr[qq * 36 + s + 4];  a1[3] = Pr[(qq + 8) * 36 + s + 4];
            #pragma unroll
            for (int nf = 0; nf < 8; nf++) {
                uint32_t bb[2];
                int c = nf * 8 + qr;
                bb[0] = V[c * 36 + s];
                bb[1] = V[c * 36 + s + 4];
                mma_tf32(o[0][nf], a0, bb);
                mma_tf32(o[1][nf], a1, bb);
            }
        }
    };
    auto SOFTMAX_P = [&](float (*sf)[4][4], uint32_t* Pw) {
        #pragma unroll
        for (int mf = 0; mf < 2; mf++) {
            float mx0 = -1e30f, mx1 = -1e30f;
            #pragma unroll
            for (int nf = 0; nf < 4; nf++) {
                mx0 = fmaxf(mx0, fmaxf(sf[mf][nf][0], sf[mf][nf][1]));
                mx1 = fmaxf(mx1, fmaxf(sf[mf][nf][2], sf[mf][nf][3]));
            }
            #pragma unroll
            for (int off = 1; off <= 2; off <<= 1) {
                mx0 = fmaxf(mx0, __shfl_xor_sync(0xffffffffu, mx0, off));
                mx1 = fmaxf(mx1, __shfl_xor_sync(0xffffffffu, mx1, off));
            }
            float nm0 = fmaxf(m_i[mf][0], mx0), nm1 = fmaxf(m_i[mf][1], mx1);
            float corr0 = ex2f(m_i[mf][0] - nm0), corr1 = ex2f(m_i[mf][1] - nm1);
            m_i[mf][0] = nm0; m_i[mf][1] = nm1;
            float lp0 = 0.f, lp1 = 0.f;
            #pragma unroll
            for (int nf = 0; nf < 4; nf++) {
                sf[mf][nf][0] = ex2f(sf[mf][nf][0] - nm0);
                sf[mf][nf][1] = ex2f(sf[mf][nf][1] - nm0);
                sf[mf][nf][2] = ex2f(sf[mf][nf][2] - nm1);
                sf[mf][nf][3] = ex2f(sf[mf][nf][3] - nm1);
                lp0 += sf[mf][nf][0] + sf[mf][nf][1];
                lp1 += sf[mf][nf][2] + sf[mf][nf][3];
            }
            l_i[mf][0] = l_i[mf][0] * corr0 + lp0;   // per-thread partial; quad-reduce deferred
            l_i[mf][1] = l_i[mf][1] * corr1 + lp1;
            #pragma unroll
            for (int nf = 0; nf < 8; nf++) {
                o[mf][nf][0] *= corr0; o[mf][nf][1] *= corr0;
                o[mf][nf][2] *= corr1; o[mf][nf][3] *= corr1;
            }
            int qq = q0 + mf * 16 + qr;
            #pragma unroll
            for (int nf = 0; nf < 4; nf++) {
                int sc = nf * 8 + 2 * qc;
                *(uint2*)&Pw[qq * 36 + sc] =
                    make_uint2(f2tf32(sf[mf][nf][0]), f2tf32(sf[mf][nf][1]));
                *(uint2*)&Pw[(qq + 8) * 36 + sc] =
                    make_uint2(f2tf32(sf[mf][nf][2]), f2tf32(sf[mf][nf][3]));
            }
        }
        __syncwarp();
    };

    // chunk 0: S + softmax only (pipeline fill)
    cp_wait<1>();
    __syncthreads();   // chunk0 KV ready; also fences Q-hoist reads before Pb[0] writes
    {
        float sf[2][4][4] = {};
        S_MMA(Ksl[0], sf);
        SOFTMAX_P(sf, Pb[0]);
    }
    ISSUE_KV(2, 2, 64);
    cp_commit();

    // steady state: iteration j does S(j+1) + PV(j)
    #pragma unroll 1
    for (int j = 0; j < 31; j++) {
        if (j < 30) { cp_wait<1>(); } else { cp_wait<0>(); }
        __syncthreads();   // K(j+1)/V ready; fences readers of reused ring slots

        float sf[2][4][4] = {};
        S_MMA(Ksl[(j + 1) % 3], sf);
        PV_MMA(Pb[j & 1], Vsl[j & 3]);
        SOFTMAX_P(sf, Pb[(j + 1) & 1]);

        if (j + 3 < 32) ISSUE_KV((j + 3) % 3, (j + 3) & 3, (j + 3) << 5);
        cp_commit();
    }
    // drain: PV for chunk 31
    PV_MMA(Pb[1], Vsl[3]);

    // ---- epilogue: quad-reduce l, normalize, stage [c][t] stride 132, store ----
    float inv[2][2];
    #pragma unroll
    for (int mf = 0; mf < 2; mf++)
        #pragma unroll
        for (int r2 = 0; r2 < 2; r2++) {
            float l = l_i[mf][r2];
            l += __shfl_xor_sync(0xffffffffu, l, 1);
            l += __shfl_xor_sync(0xffffffffu, l, 2);
            inv[mf][r2] = 1.f / l;
        }
    __syncthreads();   // all warps done with P buffers before O staging reuse
    float* Os = (float*)smw;
    #pragma unroll
    for (int mf = 0; mf < 2; mf++) {
        float i0 = inv[mf][0], i1 = inv[mf][1];
        int qq = q0 + mf * 16 + qr;
        #pragma unroll
        for (int nf = 0; nf < 8; nf++) {
            int c = nf * 8 + 2 * qc;
            Os[c * 132 + qq]           = tf32f(o[mf][nf][0] * i0);
            Os[(c + 1) * 132 + qq]     = tf32f(o[mf][nf][1] * i0);
            Os[c * 132 + qq + 8]       = tf32f(o[mf][nf][2] * i1);
            Os[(c + 1) * 132 + qq + 8] = tf32f(o[mf][nf][3] * i1);
        }
    }
    __syncthreads();
    float* outp = g_attn + ((size_t)b * NC + (size_t)h * NCH) * NT;
    #pragma unroll
    for (int r = 0; r < 16; r++) {
        int idx = tid + (r << 7);
        int c = idx >> 5, t4 = (idx & 31) << 2;
        *(float4*)(outp + (size_t)c * NT + qt0 + t4) = *(const float4*)&Os[c * 132 + t4];
    }
}

// ---------------- launch ----------------
extern "C" void kernel_launch(void* const* d_in, const int* in_sizes, int n_in,
                              void* d_out, int out_size) {
    const float* x      = (const float*)d_in[0];
    const float* norm_w = (const float*)d_in[1];
    const float* norm_b = (const float*)d_in[2];
    const float* qkv_w  = (const float*)d_in[3];
    const float* qkv_b  = (const float*)d_in[4];
    const float* proj_w = (const float*)d_in[5];
    const float* proj_b = (const float*)d_in[6];
    float* out = (float*)d_out;

    float *xn_p, *wq_p, *wp_p, *qkv_p, *attn_p;
    cudaGetSymbolAddress((void**)&xn_p, g_xn);
    cudaGetSymbolAddress((void**)&wq_p, g_wq);
    cudaGetSymbolAddress((void**)&wp_p, g_wp);
    cudaGetSymbolAddress((void**)&qkv_p, g_qkv);
    cudaGetSymbolAddress((void**)&attn_p, g_attn);

    const int gemm_smem = 3 * 8448 * 4;   // 101376
    cudaFuncSetAttribute(mma_gemm_kernel<3 * NC, true, false>,
                         cudaFuncAttributeMaxDynamicSharedMemorySize, gemm_smem);
    cudaFuncSetAttribute(mma_gemm_kernel<NC, false, true>,
                         cudaFuncAttributeMaxDynamicSharedMemorySize, gemm_smem);
    const int attn_smem = 25344 * 4;      // 101376
    cudaFuncSetAttribute(attn_kernel, cudaFuncAttributeMaxDynamicSharedMemorySize, attn_smem);

    wperm_kernel<<<(3 * NC / 128) * 16, 256>>>(qkv_w, wq_p);
    wperm_kernel<<<(NC / 128) * 16, 256>>>(proj_w, wp_p);
    gn_kernel<<<NB * NGROUPS, 256>>>(x, norm_w, norm_b);

    dim3 gq(NT / 128, (3 * NC) / 128, NB);
    mma_gemm_kernel<3 * NC, true, false><<<gq, 256, gemm_smem>>>(
        wq_p, xn_p, qkv_b, nullptr, qkv_p);

    dim3 ga(NT / 128, NB * NHEADS);
    attn_kernel<<<ga, 128, attn_smem>>>();

    dim3 gp(NT / 128, NC / 128, NB);
    mma_gemm_kernel<NC, false, true><<<gp, 256, gemm_smem>>>(
        wp_p, attn_p, proj_b, x, out);
}